// round 12
// baseline (speedup 1.0000x reference)
#include <cuda_runtime.h>
#include <math.h>

// Problem constants
#define KBINS 256
#define Q 4
#define KQ (KBINS * Q)          // 1024 sub-bins
#define BATCH 8
#define NPB (512 * 512)          // 262144 elements per batch
#define NPB4 (NPB / 4)           // 65536 float4 per batch
#define CTAS_PER_BATCH 111       // 8*111 = 888 = 148*6 -> 6 CTAs/SM
#define P1_THREADS 256
#define WARPS 8
#define SCALE 4096.0f            // count-encoding scale
#define WLEN 32                  // convolution window taps, jj in [-14, 17]
#define JJ_LO (-14)

#define PAD4(m) ((m) + ((m) >> 2))   // stride-4 conflict-free padding
#define KQ_PAD (KQ + (KQ >> 2))      // 1280

// One combined (cnt,rsum) histogram per batch: 8 * 1024 * 4B = 32 KB.
// Zero at module load; the finishing CTA re-zeroes it each launch.
__device__ float g_hist[BATCH * KQ];
__device__ unsigned int g_sync[BATCH];

__device__ __forceinline__ void red_add_v4(float* addr, float4 v) {
    asm volatile("red.global.add.v4.f32 [%0], {%1,%2,%3,%4};"
                 :: "l"(addr), "f"(v.x), "f"(v.y), "f"(v.z), "f"(v.w)
                 : "memory");
}

// ---------------------------------------------------------------------------
// NO-ATOMIC histogram kernel.
// Insight: the smem ATOMS unit (~1.77 cyc/lane, the R4-R11 floor) is ~30x
// slower than the smem crossbar (128 B/cyc). With PER-WARP private
// histograms, the only write races are intra-warp duplicate bins; those are
// resolved exactly with __match_any_sync + Westphal peer-reduction (shfl
// tree within each equal-bin group, warp-uniform loop). Group leaders then
// perform plain LDS+FADD+STS read-modify-writes — zero atomics in the hot
// path. Same-warp smem ops execute in issue order through the in-order
// smem pipeline, so cross-iteration RMWs to the same bin are safe.
//
// Phase A (888 CTAs, 6/SM): per-warp accumulate (cnt,rsum)-encoded values
//   (val = SCALE + r); CTA-reduce the 8 warp histograms; one v4-REDG per
//   thread into the per-batch global histogram.
// Phase B (last CTA per batch): decode, 32-tap first-order-corrected
//   convolution, write 256 outputs, reset state for graph replay.
// ---------------------------------------------------------------------------
__global__ void __launch_bounds__(P1_THREADS, 6)
hist_fused(const float* __restrict__ x, float* __restrict__ out) {
    __shared__ float whist[WARPS * KQ];     // 32 KB; phase B overlays here
    __shared__ bool is_last;

    const int tid = threadIdx.x;
    const int lane = tid & 31;
    const int wid = tid >> 5;
    const int b = blockIdx.y;
    const int c = blockIdx.x;

    // Zero the per-warp histograms (8192 floats -> 8 float4 stores/thread).
    #pragma unroll
    for (int i = tid; i < WARPS * KQ / 4; i += P1_THREADS)
        ((float4*)whist)[i] = make_float4(0.f, 0.f, 0.f, 0.f);
    __syncthreads();

    volatile float* wh = whist + wid * KQ;  // this warp's private histogram

    // --- Phase A over this CTA's balanced range (uniform iteration count
    //     so every warp stays fully converged for the match intrinsics) ---
    const float4* __restrict__ xp = reinterpret_cast<const float4*>(x) + (size_t)b * NPB4;
    const int i_lo = (c * NPB4) / CTAS_PER_BATCH;
    const int i_hi = ((c + 1) * NPB4) / CTAS_PER_BATCH;
    const int iters = (i_hi - i_lo + P1_THREADS - 1) / P1_THREADS;

    for (int it = 0; it < iters; it++) {
        int i = i_lo + it * P1_THREADS + tid;
        bool act = (i < i_hi);
        float4 v = act ? xp[i] : make_float4(0.f, 0.f, 0.f, 0.f);
        float vals[4] = {v.x, v.y, v.z, v.w};
        #pragma unroll
        for (int j = 0; j < 4; j++) {
            float u = vals[j] * (float)KQ;          // sub-bin position
            int idx = __float2int_rd(u);
            idx = max(0, min(KQ - 1, idx));
            float enc = u - (float)idx + (SCALE - 0.5f);  // cnt + residual
            int key = act ? idx : -1;               // inactive lanes group apart

            // Group lanes with equal bin; reduce each group onto its leader.
            unsigned peers = __match_any_sync(0xffffffffu, key);
            int first = __ffs(peers) - 1;           // group leader lane
            unsigned rel = __popc(peers & ((1u << lane) - 1)); // rank in group
            unsigned above = peers & (0xfffffffeu << lane);    // peers above me
            while (__any_sync(0xffffffffu, above != 0)) {
                int nxt = __ffs(above);             // 1-based; 0 if none
                float t = __shfl_sync(0xffffffffu, enc, (nxt - 1) & 31);
                if (above) enc += t;
                unsigned alive = __ballot_sync(0xffffffffu, !(rel & 1));
                above &= alive;                     // drop consumed (odd-rank) lanes
                rel >>= 1;
            }

            // Leader does a plain smem RMW — addresses are unique per warp.
            if (act && lane == first) {
                wh[idx] = wh[idx] + enc;            // LDS + FADD + STS
            }
        }
    }
    __syncthreads();

    // CTA-reduce the 8 warp histograms, flush with one v4-REDG per thread.
    float* __restrict__ gh = g_hist + (size_t)b * KQ;
    {
        float4 s = make_float4(0.f, 0.f, 0.f, 0.f);
        #pragma unroll
        for (int w = 0; w < WARPS; w++) {
            float4 h = *(const float4*)&whist[w * KQ + tid * 4];
            s.x += h.x; s.y += h.y; s.z += h.z; s.w += h.w;
        }
        red_add_v4(&gh[tid * 4], s);
    }

    // --- Arrival protocol: last CTA of this batch proceeds to phase B ---
    __threadfence();
    if (tid == 0) {
        unsigned int old = atomicAdd(&g_sync[b], 1u);
        is_last = (old == CTAS_PER_BATCH - 1);
    }
    __syncthreads();
    if (!is_last) return;

    // --- Phase B: decode + convolution (one CTA per batch) ---
    float* pool  = whist;                    // reuse smem
    float* s_cnt = pool;                     // [KQ_PAD]
    float* s_rs  = pool + KQ_PAD;            // [KQ_PAD]
    float* s_w0  = pool + 2 * KQ_PAD;        // [WLEN]
    float* s_w1  = s_w0 + WLEN;              // [WLEN]

    #pragma unroll
    for (int m = tid; m < KQ; m += P1_THREADS) {
        float s = __ldcg(&gh[m]);            // L2-coherent read
        float cnt = rintf(s * (1.0f / SCALE));
        float rs  = s - cnt * SCALE;
        s_cnt[PAD4(m)] = cnt;
        s_rs[PAD4(m)]  = rs;
        gh[m] = 0.0f;                        // reset for next graph replay
    }
    if (tid == 0) g_sync[b] = 0u;

    // Window weights. With Q=4: a+ = 0.625*(jj+0.5), a- = 0.625*(jj-3.5)
    if (tid < WLEN) {
        float jj = (float)(tid + JJ_LO);
        float ap = 0.625f * (jj + 0.5f);
        float am = 0.625f * (jj - 3.5f);
        float sp = 1.0f / (1.0f + __expf(-ap));
        float sm = 1.0f / (1.0f + __expf(-am));
        s_w0[tid] = sp - sm;
        s_w1[tid] = (sp * (1.0f - sp) - sm * (1.0f - sm)) * 0.625f;
    }
    __syncthreads();

    // 32-tap convolution per output bin (thread tid = bin k).
    const int base = tid * Q + JJ_LO;
    float acc = 0.0f;
    #pragma unroll
    for (int w = 0; w < WLEN; w++) {
        int m = base + w;
        if (m >= 0 && m < KQ) {
            int mp = PAD4(m);
            acc = fmaf(s_cnt[mp], s_w0[w], acc);
            acc = fmaf(s_rs[mp],  s_w1[w], acc);
        }
    }
    out[b * KBINS + tid] = acc * (1.0f / (float)NPB);
}

extern "C" void kernel_launch(void* const* d_in, const int* in_sizes, int n_in,
                              void* d_out, int out_size) {
    (void)in_sizes; (void)n_in; (void)out_size;
    const float* x = (const float*)d_in[0];
    float* out = (float*)d_out;
    dim3 grid(CTAS_PER_BATCH, BATCH);
    hist_fused<<<grid, P1_THREADS>>>(x, out);
}

// round 13
// speedup vs baseline: 1.7461x; 1.7461x over previous
#include <cuda_runtime.h>
#include <math.h>

// Problem constants
#define KBINS 256
#define Q 4
#define KQ (KBINS * Q)          // 1024 sub-bins
#define BATCH 8
#define NPB (512 * 512)          // 262144 elements per batch
#define NPB4 (NPB / 4)           // 65536 float4 per batch
#define CTAS_PER_BATCH 148       // 8*148 = 1184 = 148*8 -> exactly 8 CTAs/SM
#define P1_THREADS 256
#define SCALE 4096.0f            // count-encoding scale
#define WLEN 32                  // convolution window taps, jj in [-14, 17]
#define JJ_LO (-14)

#define PAD4(m) ((m) + ((m) >> 2))   // stride-4 conflict-free padding
#define KQ_PAD (KQ + (KQ >> 2))      // 1280

// One combined (cnt,rsum) histogram per batch: 8 * 1024 * 4B = 32 KB.
// Zero at module load; the finishing CTA re-zeroes it each launch so the
// kernel is graph-replay deterministic.
__device__ float g_hist[BATCH * KQ];
__device__ unsigned int g_sync[BATCH];

__device__ __forceinline__ void red_add_v4(float* addr, float4 v) {
    asm volatile("red.global.add.v4.f32 [%0], {%1,%2,%3,%4};"
                 :: "l"(addr), "f"(v.x), "f"(v.y), "f"(v.z), "f"(v.w)
                 : "memory");
}

// ---------------------------------------------------------------------------
// FINAL — pure shared-ATOMS at the measured smem-atomic-port floor.
// Evidence across R4-R12:
//   * ATOMS saturates at ~1.74 cyc/atomic (kernel time == atomic stream).
//   * One ATOMS per element is the algorithmic minimum for 1024-bin
//     accumulation of uniform data.
//   * L2-atomic offload strictly worse in all mixtures (R5: 3.2 cyc/elem
//     pure; R6: additive via shared per-SM L1tex FIFO; R8: collapses at low
//     requester count).
//   * Software conflict resolution (match_any + shfl reduction + plain RMW,
//     R12) costs 3.36 cyc/elem — hardware ATOMS wins 1.9x.
//   * 8 CTAs/SM (R11) hides LDG reload bubbles and finish skew: occ 93%.
//
// Phase A (1184 CTAs, perfectly balanced, 8/SM): quantize each x into one
//   of 1024 sub-bins; ONE shared atomicAdd per element encoding (count,
//   residual): val = SCALE + r, r in [-0.5, 0.5] sub-bin units. Flush the
//   4KB shared histogram with one red.global.add.v4.f32 per thread.
// Phase B (last CTA per batch): read the 4KB batch histogram from L2,
//   decode (cnt, rsum), 32-tap first-order-corrected convolution, write
//   256 outputs, reset state for graph replay.
// ---------------------------------------------------------------------------
__global__ void __launch_bounds__(P1_THREADS, 8)
hist_fused(const float* __restrict__ x, float* __restrict__ out) {
    __shared__ float pool[2 * KQ_PAD + 2 * WLEN];   // phase A uses first KQ
    __shared__ bool is_last;
    float* sh = pool;

    const int tid = threadIdx.x;
    const int b = blockIdx.y;
    const int c = blockIdx.x;

    ((float4*)sh)[tid] = make_float4(0.f, 0.f, 0.f, 0.f);
    __syncthreads();

    // --- Phase A: local accumulation over this CTA's balanced range ---
    const float4* __restrict__ xp = reinterpret_cast<const float4*>(x) + (size_t)b * NPB4;
    const int i_lo = (c * NPB4) / CTAS_PER_BATCH;
    const int i_hi = ((c + 1) * NPB4) / CTAS_PER_BATCH;

    #pragma unroll 2
    for (int i = i_lo + tid; i < i_hi; i += P1_THREADS) {
        float4 v = xp[i];
        float vals[4] = {v.x, v.y, v.z, v.w};
        #pragma unroll
        for (int j = 0; j < 4; j++) {
            float u = vals[j] * (float)KQ;        // position in sub-bin units
            int idx = __float2int_rd(u);          // floor as direct F2I.FLOOR
            idx = max(0, min(KQ - 1, idx));
            // one ATOMS per element: count (SCALE) + residual (u - idx - 0.5)
            atomicAdd(&sh[idx], u - (float)idx + (SCALE - 0.5f));
        }
    }
    __syncthreads();

    // Flush: one v4 reduction per thread (1024 bins / 4 / 256 threads).
    float* __restrict__ gh = g_hist + (size_t)b * KQ;
    {
        float4 vv = ((const float4*)sh)[tid];
        red_add_v4(&gh[tid * 4], vv);
    }

    // --- Arrival protocol: last CTA of this batch proceeds to phase B ---
    __threadfence();
    if (tid == 0) {
        unsigned int old = atomicAdd(&g_sync[b], 1u);
        is_last = (old == CTAS_PER_BATCH - 1);
    }
    __syncthreads();
    if (!is_last) return;

    // --- Phase B: decode + convolution (one CTA per batch) ---
    float* s_cnt = pool;                    // [KQ_PAD]
    float* s_rs  = pool + KQ_PAD;           // [KQ_PAD]
    float* s_w0  = pool + 2 * KQ_PAD;       // [WLEN]
    float* s_w1  = s_w0 + WLEN;             // [WLEN]

    #pragma unroll
    for (int m = tid; m < KQ; m += P1_THREADS) {
        float s = __ldcg(&gh[m]);           // L2-coherent read
        float cnt = rintf(s * (1.0f / SCALE));
        float rs  = s - cnt * SCALE;
        s_cnt[PAD4(m)] = cnt;
        s_rs[PAD4(m)]  = rs;
        gh[m] = 0.0f;                       // reset for next graph replay
    }
    if (tid == 0) g_sync[b] = 0u;

    // Window weights (float). With Q=4, Delta = 1/1024:
    //   a+ = 0.625*(jj + 0.5), a- = 0.625*(jj - 3.5)
    //   w0 = sigmoid(a+) - sigmoid(a-);  w1 = 0.625*[sig'(a+) - sig'(a-)]
    if (tid < WLEN) {
        float jj = (float)(tid + JJ_LO);
        float ap = 0.625f * (jj + 0.5f);
        float am = 0.625f * (jj - 3.5f);
        float sp = 1.0f / (1.0f + __expf(-ap));
        float sm = 1.0f / (1.0f + __expf(-am));
        s_w0[tid] = sp - sm;
        s_w1[tid] = (sp * (1.0f - sp) - sm * (1.0f - sm)) * 0.625f;
    }
    __syncthreads();

    // 32-tap convolution per output bin (thread tid = bin k).
    const int base = tid * Q + JJ_LO;
    float acc = 0.0f;
    #pragma unroll
    for (int w = 0; w < WLEN; w++) {
        int m = base + w;
        if (m >= 0 && m < KQ) {
            int mp = PAD4(m);
            acc = fmaf(s_cnt[mp], s_w0[w], acc);
            acc = fmaf(s_rs[mp],  s_w1[w], acc);
        }
    }
    out[b * KBINS + tid] = acc * (1.0f / (float)NPB);
}

extern "C" void kernel_launch(void* const* d_in, const int* in_sizes, int n_in,
                              void* d_out, int out_size) {
    (void)in_sizes; (void)n_in; (void)out_size;
    const float* x = (const float*)d_in[0];
    float* out = (float*)d_out;
    dim3 grid(CTAS_PER_BATCH, BATCH);
    hist_fused<<<grid, P1_THREADS>>>(x, out);
}

// round 14
// speedup vs baseline: 1.9649x; 1.1253x over previous
#include <cuda_runtime.h>
#include <math.h>

// Problem constants
#define KBINS 256
#define Q 4
#define KQ (KBINS * Q)          // 1024 sub-bins
#define BATCH 8
#define NPB (512 * 512)          // 262144 elements per batch
#define NPB4 (NPB / 4)           // 65536 float4 per batch
#define CTAS_PER_BATCH 148       // 8*148 = 1184 = 148*8 -> exactly 8 CTAs/SM
#define P1_THREADS 256
#define SCALE 4096.0f            // count-encoding scale
#define WLEN 32                  // convolution window taps, jj in [-14, 17]
#define JJ_LO (-14)

#define PAD4(m) ((m) + ((m) >> 2))   // stride-4 conflict-free padding
#define KQ_PAD (KQ + (KQ >> 2))      // 1280

// One combined (cnt,rsum) histogram per batch: 8 * 1024 * 4B = 32 KB.
// Zero at module load; the finishing CTA re-zeroes it each launch so the
// kernel is graph-replay deterministic.
__device__ float g_hist[BATCH * KQ];
__device__ unsigned int g_sync[BATCH];

__device__ __forceinline__ void red_add_v4(float* addr, float4 v) {
    asm volatile("red.global.add.v4.f32 [%0], {%1,%2,%3,%4};"
                 :: "l"(addr), "f"(v.x), "f"(v.y), "f"(v.z), "f"(v.w)
                 : "memory");
}

// ---------------------------------------------------------------------------
// FINAL (converged) — pure shared-ATOMS at the measured smem-atomic-port
// floor. Evidence across R4-R13:
//   * ATOMS saturates at ~1.74 cyc/atomic; kernel time equals the atomic
//     stream cycle count to within 1% (12.1-12.3 us, reproducible).
//   * One ATOMS per element is the algorithmic minimum for 1024-bin
//     accumulation of uniform data; subsampling fails the 1e-3 budget.
//   * L2-atomic offload strictly worse in all mixtures (R5 pure: 3.2
//     cyc/elem; R6 intra-SM mix: additive via shared L1tex FIFO; R8
//     SM-partitioned: REDG collapses at low requester count).
//   * Software conflict resolution (match_any + shfl + plain RMW, R12):
//     3.36 cyc/elem — hardware ATOMS wins 1.9x.
//   * 8 CTAs/SM hides LDG reload bubbles and finish skew (occ ~90%).
// Remaining total-vs-kernel gap (0.7-2.1 us) is harness/launch overhead.
//
// Phase A (1184 CTAs, perfectly balanced, 8/SM): quantize each x into one
//   of 1024 sub-bins; ONE shared atomicAdd per element encoding (count,
//   residual): val = SCALE + r, r in [-0.5, 0.5] sub-bin units. Flush the
//   4KB shared histogram with one red.global.add.v4.f32 per thread.
// Phase B (last CTA per batch): read the 4KB batch histogram from L2,
//   decode (cnt, rsum), 32-tap first-order-corrected convolution, write
//   256 outputs, reset state for graph replay.
// ---------------------------------------------------------------------------
__global__ void __launch_bounds__(P1_THREADS, 8)
hist_fused(const float* __restrict__ x, float* __restrict__ out) {
    __shared__ float pool[2 * KQ_PAD + 2 * WLEN];   // phase A uses first KQ
    __shared__ bool is_last;
    float* sh = pool;

    const int tid = threadIdx.x;
    const int b = blockIdx.y;
    const int c = blockIdx.x;

    ((float4*)sh)[tid] = make_float4(0.f, 0.f, 0.f, 0.f);
    __syncthreads();

    // --- Phase A: local accumulation over this CTA's balanced range ---
    const float4* __restrict__ xp = reinterpret_cast<const float4*>(x) + (size_t)b * NPB4;
    const int i_lo = (c * NPB4) / CTAS_PER_BATCH;
    const int i_hi = ((c + 1) * NPB4) / CTAS_PER_BATCH;

    #pragma unroll 2
    for (int i = i_lo + tid; i < i_hi; i += P1_THREADS) {
        float4 v = xp[i];
        float vals[4] = {v.x, v.y, v.z, v.w};
        #pragma unroll
        for (int j = 0; j < 4; j++) {
            float u = vals[j] * (float)KQ;        // position in sub-bin units
            int idx = __float2int_rd(u);          // floor as direct F2I.FLOOR
            idx = max(0, min(KQ - 1, idx));
            // one ATOMS per element: count (SCALE) + residual (u - idx - 0.5)
            atomicAdd(&sh[idx], u - (float)idx + (SCALE - 0.5f));
        }
    }
    __syncthreads();

    // Flush: one v4 reduction per thread (1024 bins / 4 / 256 threads).
    float* __restrict__ gh = g_hist + (size_t)b * KQ;
    {
        float4 vv = ((const float4*)sh)[tid];
        red_add_v4(&gh[tid * 4], vv);
    }

    // --- Arrival protocol: last CTA of this batch proceeds to phase B ---
    __threadfence();
    if (tid == 0) {
        unsigned int old = atomicAdd(&g_sync[b], 1u);
        is_last = (old == CTAS_PER_BATCH - 1);
    }
    __syncthreads();
    if (!is_last) return;

    // --- Phase B: decode + convolution (one CTA per batch) ---
    float* s_cnt = pool;                    // [KQ_PAD]
    float* s_rs  = pool + KQ_PAD;           // [KQ_PAD]
    float* s_w0  = pool + 2 * KQ_PAD;       // [WLEN]
    float* s_w1  = s_w0 + WLEN;             // [WLEN]

    #pragma unroll
    for (int m = tid; m < KQ; m += P1_THREADS) {
        float s = __ldcg(&gh[m]);           // L2-coherent read
        float cnt = rintf(s * (1.0f / SCALE));
        float rs  = s - cnt * SCALE;
        s_cnt[PAD4(m)] = cnt;
        s_rs[PAD4(m)]  = rs;
        gh[m] = 0.0f;                       // reset for next graph replay
    }
    if (tid == 0) g_sync[b] = 0u;

    // Window weights (float). With Q=4, Delta = 1/1024:
    //   a+ = 0.625*(jj + 0.5), a- = 0.625*(jj - 3.5)
    //   w0 = sigmoid(a+) - sigmoid(a-);  w1 = 0.625*[sig'(a+) - sig'(a-)]
    if (tid < WLEN) {
        float jj = (float)(tid + JJ_LO);
        float ap = 0.625f * (jj + 0.5f);
        float am = 0.625f * (jj - 3.5f);
        float sp = 1.0f / (1.0f + __expf(-ap));
        float sm = 1.0f / (1.0f + __expf(-am));
        s_w0[tid] = sp - sm;
        s_w1[tid] = (sp * (1.0f - sp) - sm * (1.0f - sm)) * 0.625f;
    }
    __syncthreads();

    // 32-tap convolution per output bin (thread tid = bin k).
    const int base = tid * Q + JJ_LO;
    float acc = 0.0f;
    #pragma unroll
    for (int w = 0; w < WLEN; w++) {
        int m = base + w;
        if (m >= 0 && m < KQ) {
            int mp = PAD4(m);
            acc = fmaf(s_cnt[mp], s_w0[w], acc);
            acc = fmaf(s_rs[mp],  s_w1[w], acc);
        }
    }
    out[b * KBINS + tid] = acc * (1.0f / (float)NPB);
}

extern "C" void kernel_launch(void* const* d_in, const int* in_sizes, int n_in,
                              void* d_out, int out_size) {
    (void)in_sizes; (void)n_in; (void)out_size;
    const float* x = (const float*)d_in[0];
    float* out = (float*)d_out;
    dim3 grid(CTAS_PER_BATCH, BATCH);
    hist_fused<<<grid, P1_THREADS>>>(x, out);
}